// round 14
// baseline (speedup 1.0000x reference)
#include <cuda_runtime.h>
#include <cuda_bf16.h>
#include <cstdint>

#define DDIM 256
#define TLEN 4096
#define KCB  1024
#define TM   128
#define CAP  32
#define TAU  0.28f
#define NCH  16      // chunks of 64 codes (int8: 16KB each)

// smem map
#define REGION_OFF 0        // 66048B: fp32 staging [64][257]; cb double buf 2x16KB
#define CB_STRIDE  16384
#define CSQ_OFF    66048    // 1024 floats
#define SCNT_OFF   70144    // 128 ints
#define CAND_OFF   70656    // 128*32 ints
#define BESTI_OFF  87040    // 128 ints
#define PMAX_OFF   87552    // 64*16 floats
#define SZ_OFF     91648    // 128 floats (qz per token)
#define SMEMF      92160

__device__ __align__(16) signed char g_cb8[KCB * DDIM];
__device__ float g_csq[KCB];
__device__ unsigned int g_cmax = 0u;

// ---------------- helpers ----------------
__device__ __forceinline__ uint32_t smem_u32(const void* p) {
    uint32_t a;
    asm("{ .reg .u64 t; cvta.to.shared.u64 t, %1; cvt.u32.u64 %0, t; }" : "=r"(a) : "l"(p));
    return a;
}
__device__ __forceinline__ void ldsm_x4(uint32_t* r, uint32_t a) {
    asm volatile("ldmatrix.sync.aligned.m8n8.x4.shared.b16 {%0,%1,%2,%3}, [%4];"
        : "=r"(r[0]), "=r"(r[1]), "=r"(r[2]), "=r"(r[3]) : "r"(a));
}
__device__ __forceinline__ void imma16832(int* c, const uint32_t* a,
                                          uint32_t b0, uint32_t b1) {
    asm volatile("mma.sync.aligned.m16n8k32.row.col.s32.s8.s8.s32 "
        "{%0,%1,%2,%3}, {%4,%5,%6,%7}, {%8,%9}, {%0,%1,%2,%3};"
        : "+r"(c[0]), "+r"(c[1]), "+r"(c[2]), "+r"(c[3])
        : "r"(a[0]), "r"(a[1]), "r"(a[2]), "r"(a[3]), "r"(b0), "r"(b1));
}
__device__ __forceinline__ uint32_t pack4s8(int i0, int i1, int i2, int i3) {
    uint32_t t, r;
    asm("cvt.pack.sat.s8.s32.b32 %0, %1, %2, %3;" : "=r"(t) : "r"(i3), "r"(i2), "r"(0));
    asm("cvt.pack.sat.s8.s32.b32 %0, %1, %2, %3;" : "=r"(r) : "r"(i1), "r"(i0), "r"(t));
    return r;
}
__device__ __forceinline__ void cp16(uint32_t dst, const void* src) {
    asm volatile("cp.async.cg.shared.global [%0], [%1], 16;" :: "r"(dst), "l"(src));
}
#define CP_COMMIT() asm volatile("cp.async.commit_group;" ::: "memory")
#define CP_WAIT(n)  asm volatile("cp.async.wait_group %0;" :: "n"(n) : "memory")

// ---------------- kernel 0: codebook absmax ----------------
__global__ void prep_absmax(const float* __restrict__ cb) {
    int i = (blockIdx.x * 256 + threadIdx.x) * 4;     // 256 blocks cover 262144 floats
    float4 v = *(const float4*)(cb + i);
    float m = fmaxf(fmaxf(fabsf(v.x), fabsf(v.y)), fmaxf(fabsf(v.z), fabsf(v.w)));
    #pragma unroll
    for (int o = 16; o; o >>= 1) m = fmaxf(m, __shfl_xor_sync(0xffffffffu, m, o));
    if (!(threadIdx.x & 31)) atomicMax(&g_cmax, __float_as_uint(m));
}

// ---------------- kernel 1: codebook -> int8, csq ----------------
__global__ void prep_quant(const float* __restrict__ cb) {
    int tid = threadIdx.x, wid = tid >> 5, lane = tid & 31;
    int code = blockIdx.x * 8 + wid;
    const float* row = cb + (size_t)code * DDIM;
    const float qc = fmaxf(__uint_as_float(g_cmax), 1e-20f) * (1.f / 127.f);
    const float inv = 1.f / qc;
    float4 a = *(const float4*)(row + lane * 8);
    float4 b = *(const float4*)(row + lane * 8 + 4);
    float s = a.x*a.x + a.y*a.y + a.z*a.z + a.w*a.w
            + b.x*b.x + b.y*b.y + b.z*b.z + b.w*b.w;
    #pragma unroll
    for (int o = 16; o; o >>= 1) s += __shfl_xor_sync(0xffffffffu, s, o);
    if (!lane) g_csq[code] = s;
    uint2 w;
    w.x = pack4s8(__float2int_rn(a.x*inv), __float2int_rn(a.y*inv),
                  __float2int_rn(a.z*inv), __float2int_rn(a.w*inv));
    w.y = pack4s8(__float2int_rn(b.x*inv), __float2int_rn(b.y*inv),
                  __float2int_rn(b.z*inv), __float2int_rn(b.w*inv));
    ((uint2*)(g_cb8 + (size_t)code * DDIM))[lane] = w;
}

// load 64-code int8 chunk (16KB), 4 cp.async per thread
__device__ __forceinline__ void load_chunk_async(uint32_t cbbase, int chunk, int tid) {
    const char* src = (const char*)g_cb8 + (size_t)chunk * 16384;
    #pragma unroll
    for (int i = 0; i < 4; i++) {
        int g = tid + 256 * i;                 // granule 0..1023
        int code = g >> 4, colg = g & 15;
        uint32_t dst = cbbase + code * 256 + (uint32_t)((colg ^ (code & 7)) << 4);
        cp16(dst, src + (size_t)g * 16);
    }
}

// ---------------- fused: IMMA prune + exact fp32 rescore + gather ----------------
__global__ __launch_bounds__(256, 2)
void vq_fused(const float* __restrict__ z, const float* __restrict__ cb,
              float* __restrict__ out) {
    extern __shared__ char sm[];
    uint32_t smb = smem_u32(sm);
    const uint32_t cb_b = smb + REGION_OFF;
    float* zs    = (float*)sm;                 // [64][257] fp32 staging
    float* csq_s = (float*)(sm + CSQ_OFF);
    int*   scnt  = (int*)(sm + SCNT_OFF);
    int*   cand  = (int*)(sm + CAND_OFF);
    int*   besti = (int*)(sm + BESTI_OFF);
    float* pmax  = (float*)(sm + PMAX_OFF);
    float* sz_s  = (float*)(sm + SZ_OFF);

    const int tid = threadIdx.x;
    const int wid = tid >> 5;
    const int lane = tid & 31;
    const int batch = blockIdx.x >> 5;
    const int t0 = (blockIdx.x & 31) << 7;
    const float qc = fmaxf(__uint_as_float(g_cmax), 1e-20f) * (1.f / 127.f);

    if (tid < 128) scnt[tid] = 0;
    #pragma unroll
    for (int i = tid; i < KCB; i += 256) csq_s[i] = g_csq[i];

    // ---- setup: two 64-token fp32 stages; per-token absmax; int8 B-frag build ----
    uint32_t bfr[2][8][2];    // [nt][kb][b0/b1]
    #pragma unroll 1
    for (int h = 0; h < 2; h++) {
        __syncthreads();
        const float* zb = z + (size_t)batch * DDIM * TLEN + t0 + h * 64;
        float am[4] = {0.f, 0.f, 0.f, 0.f};
        #pragma unroll
        for (int r = 0; r < 16; r++) {
            int j = tid + 256 * r;
            int d = j >> 4, t4 = (j & 15) << 2;
            float4 v = *(const float4*)(zb + (size_t)d * TLEN + t4);
            zs[(t4 + 0) * 257 + d] = v.x;
            zs[(t4 + 1) * 257 + d] = v.y;
            zs[(t4 + 2) * 257 + d] = v.z;
            zs[(t4 + 3) * 257 + d] = v.w;
            am[0] = fmaxf(am[0], fabsf(v.x));
            am[1] = fmaxf(am[1], fabsf(v.y));
            am[2] = fmaxf(am[2], fabsf(v.z));
            am[3] = fmaxf(am[3], fabsf(v.w));
        }
        {
            const int t4s = (tid & 15) << 2, sidx = tid >> 4;
            pmax[(t4s + 0) * 16 + sidx] = am[0];
            pmax[(t4s + 1) * 16 + sidx] = am[1];
            pmax[(t4s + 2) * 16 + sidx] = am[2];
            pmax[(t4s + 3) * 16 + sidx] = am[3];
        }
        __syncthreads();
        if (tid < 64) {
            float m = 0.f;
            #pragma unroll
            for (int x = 0; x < 16; x++) m = fmaxf(m, pmax[tid * 16 + x]);
            sz_s[h * 64 + tid] = fmaxf(m, 1e-20f) * (1.f / 127.f);   // qz
        }
        __syncthreads();
        if ((wid >> 2) == h) {
            const int wl = wid & 3;
            #pragma unroll
            for (int nt = 0; nt < 2; nt++) {
                const int tl = wl * 16 + nt * 8 + (lane >> 2);
                const float inv = 1.f / sz_s[h * 64 + tl];           // 127/max
                const float* row = zs + tl * 257 + (lane & 3) * 4;
                #pragma unroll
                for (int kb = 0; kb < 8; kb++) {
                    #pragma unroll
                    for (int hf = 0; hf < 2; hf++) {
                        const float* p = row + kb * 32 + hf * 16;
                        bfr[nt][kb][hf] = pack4s8(
                            __float2int_rn(p[0] * inv), __float2int_rn(p[1] * inv),
                            __float2int_rn(p[2] * inv), __float2int_rn(p[3] * inv));
                    }
                }
            }
        }
    }
    __syncthreads();   // builds done; staging region free for cb buffers

    // per-lane token score scales: scl2[nt][j] for tokens tb0+j
    float scl2[2][2];
    {
        const float c2 = -2.f * qc;
        #pragma unroll
        for (int nt = 0; nt < 2; nt++) {
            const int tb0 = wid * 16 + nt * 8 + (lane & 3) * 2;
            scl2[nt][0] = c2 * sz_s[tb0];
            scl2[nt][1] = c2 * sz_s[tb0 + 1];
        }
    }

    // start codebook chunk pipeline
    load_chunk_async(cb_b, 0, tid);             CP_COMMIT();
    load_chunk_async(cb_b + CB_STRIDE, 1, tid); CP_COMMIT();

    float rm[2][2] = {{3.4e38f, 3.4e38f}, {3.4e38f, 3.4e38f}};
    const int arow7 = (lane & 7) + ((lane & 8) ? 8 : 0);
    const uint32_t hi = (uint32_t)(lane >> 4);

    for (int c = 0; c < NCH; c++) {
        if (c < NCH - 1) CP_WAIT(1); else CP_WAIT(0);
        __syncthreads();
        const uint32_t cbc = cb_b + (uint32_t)(c & 1) * CB_STRIDE;

        #pragma unroll
        for (int mb = 0; mb < 4; mb++) {
            int acc[2][2][4];
            #pragma unroll
            for (int n = 0; n < 2; n++)
                #pragma unroll
                for (int p = 0; p < 2; p++)
                    #pragma unroll
                    for (int r = 0; r < 4; r++) acc[n][p][r] = 0;

            const int arow = mb * 16 + arow7;
            const uint32_t abase = cbc + (uint32_t)arow * 256;
            const uint32_t sw = (uint32_t)(arow & 7);
            #pragma unroll
            for (int kb = 0; kb < 8; kb++) {
                uint32_t ar[4];
                const uint32_t g = ((uint32_t)kb << 1) | hi;
                ldsm_x4(ar, abase + ((g ^ sw) << 4));
                imma16832(acc[0][kb & 1], ar, bfr[0][kb][0], bfr[0][kb][1]);
                imma16832(acc[1][kb & 1], ar, bfr[1][kb][0], bfr[1][kb][1]);
            }

            const int cA = c * 64 + mb * 16 + (lane >> 2);
            const int cB = cA + 8;
            const float qA = csq_s[cA];
            const float qB = csq_s[cB];
            float ss[2][4], pp[2][2];
            #pragma unroll
            for (int nt = 0; nt < 2; nt++) {
                float f0 = (float)(acc[nt][0][0] + acc[nt][1][0]);
                float f1 = (float)(acc[nt][0][1] + acc[nt][1][1]);
                float f2 = (float)(acc[nt][0][2] + acc[nt][1][2]);
                float f3 = (float)(acc[nt][0][3] + acc[nt][1][3]);
                ss[nt][0] = fmaf(scl2[nt][0], f0, qA);
                ss[nt][1] = fmaf(scl2[nt][1], f1, qA);
                ss[nt][2] = fmaf(scl2[nt][0], f2, qB);
                ss[nt][3] = fmaf(scl2[nt][1], f3, qB);
                pp[nt][0] = fminf(ss[nt][0], ss[nt][2]);
                pp[nt][1] = fminf(ss[nt][1], ss[nt][3]);
                rm[nt][0] = fminf(rm[nt][0], pp[nt][0]);
                rm[nt][1] = fminf(rm[nt][1], pp[nt][1]);
            }
            // rotating-stride min diffusion (rm stays a valid upper bound)
            {
                const int off = 4 << ((c * 4 + mb) % 3);
                #pragma unroll
                for (int nt = 0; nt < 2; nt++) {
                    rm[nt][0] = fminf(rm[nt][0], __shfl_xor_sync(0xffffffffu, rm[nt][0], off));
                    rm[nt][1] = fminf(rm[nt][1], __shfl_xor_sync(0xffffffffu, rm[nt][1], off));
                }
            }
            #pragma unroll
            for (int nt = 0; nt < 2; nt++) {
                const int tb0 = wid * 16 + nt * 8 + (lane & 3) * 2;
                const float th0 = rm[nt][0] + TAU;
                const float th1 = rm[nt][1] + TAU;
                if (pp[nt][0] < th0) {
                    if (ss[nt][0] < th0) {
                        int p = atomicAdd(&scnt[tb0], 1);
                        if (p < CAP) cand[tb0 * CAP + p] = cA;
                    }
                    if (ss[nt][2] < th0) {
                        int p = atomicAdd(&scnt[tb0], 1);
                        if (p < CAP) cand[tb0 * CAP + p] = cB;
                    }
                }
                if (pp[nt][1] < th1) {
                    if (ss[nt][1] < th1) {
                        int p = atomicAdd(&scnt[tb0 + 1], 1);
                        if (p < CAP) cand[(tb0 + 1) * CAP + p] = cA;
                    }
                    if (ss[nt][3] < th1) {
                        int p = atomicAdd(&scnt[tb0 + 1], 1);
                        if (p < CAP) cand[(tb0 + 1) * CAP + p] = cB;
                    }
                }
            }
        }
        __syncthreads();
        if (c + 2 < NCH) { load_chunk_async(cbc, c + 2, tid); CP_COMMIT(); }
    }

    // ================= fused exact fp32 rescore (two 64-token passes) =================
    #pragma unroll 1
    for (int h = 0; h < 2; h++) {
        __syncthreads();
        const float* zb = z + (size_t)batch * DDIM * TLEN + t0 + h * 64;
        #pragma unroll
        for (int r = 0; r < 16; r++) {
            int j = tid + 256 * r;
            int d = j >> 4, t4 = (j & 15) << 2;
            float4 v = *(const float4*)(zb + (size_t)d * TLEN + t4);
            zs[(t4 + 0) * 257 + d] = v.x;
            zs[(t4 + 1) * 257 + d] = v.y;
            zs[(t4 + 2) * 257 + d] = v.z;
            zs[(t4 + 3) * 257 + d] = v.w;
        }
        __syncthreads();

        for (int tt = 0; tt < 8; tt++) {
            const int tl = wid * 8 + tt;
            const int tok = h * 64 + tl;
            int cnt = scnt[tok];
            const bool full = cnt > CAP;       // overflow: exact full-scan fallback
            if (full) cnt = KCB;
            if (cnt == 1) {
                if (!lane) besti[tok] = cand[tok * CAP];
                continue;
            }
            float zr[8];
            #pragma unroll
            for (int q = 0; q < 8; q++) zr[q] = zs[tl * 257 + lane + 32 * q];
            float bv = 3.4028235e38f; int bi = 0;
            int j = 0;
            for (; j + 1 < cnt; j += 2) {
                const int k0 = full ? j     : cand[tok * CAP + j];
                const int k1 = full ? j + 1 : cand[tok * CAP + j + 1];
                const float* c0 = cb + (size_t)k0 * DDIM + lane;
                const float* c1 = cb + (size_t)k1 * DDIM + lane;
                float d0 = 0.f, d1 = 0.f;
                #pragma unroll
                for (int q = 0; q < 8; q++) {
                    d0 = fmaf(zr[q], c0[32 * q], d0);
                    d1 = fmaf(zr[q], c1[32 * q], d1);
                }
                #pragma unroll
                for (int o = 16; o; o >>= 1) {
                    d0 += __shfl_xor_sync(0xffffffffu, d0, o);
                    d1 += __shfl_xor_sync(0xffffffffu, d1, o);
                }
                float s0 = fmaf(-2.f, d0, csq_s[k0]);
                float s1 = fmaf(-2.f, d1, csq_s[k1]);
                if (s0 < bv || (s0 == bv && k0 < bi)) { bv = s0; bi = k0; }
                if (s1 < bv || (s1 == bv && k1 < bi)) { bv = s1; bi = k1; }
            }
            if (j < cnt) {
                const int k0 = full ? j : cand[tok * CAP + j];
                const float* c0 = cb + (size_t)k0 * DDIM + lane;
                float d0 = 0.f;
                #pragma unroll
                for (int q = 0; q < 8; q++) d0 = fmaf(zr[q], c0[32 * q], d0);
                #pragma unroll
                for (int o = 16; o; o >>= 1) d0 += __shfl_xor_sync(0xffffffffu, d0, o);
                float s0 = fmaf(-2.f, d0, csq_s[k0]);
                if (s0 < bv || (s0 == bv && k0 < bi)) { bv = s0; bi = k0; }
            }
            if (!lane) besti[tok] = bi;
        }
    }

    // ================= gather (two 64-token passes, coalesced both sides) =================
    #pragma unroll 1
    for (int h = 0; h < 2; h++) {
        __syncthreads();
        for (int j = tid; j < 64 * 64; j += 256) {
            int t = j >> 6, f4 = (j & 63) << 2;
            float4 v = *(const float4*)(cb + (size_t)besti[h * 64 + t] * DDIM + f4);
            float* p = zs + t * 257 + f4;
            p[0] = v.x; p[1] = v.y; p[2] = v.z; p[3] = v.w;
        }
        __syncthreads();
        float* ob = out + (size_t)batch * DDIM * TLEN + t0 + h * 64;
        for (int i = tid; i < DDIM * 64; i += 256) {
            int d = i >> 6, t = i & 63;
            ob[(size_t)d * TLEN + t] = zs[t * 257 + d];
        }
    }
}

extern "C" void kernel_launch(void* const* d_in, const int* in_sizes, int n_in,
                              void* d_out, int out_size) {
    const float* z  = (const float*)d_in[0];
    const float* cb = (const float*)d_in[1];
    float* out = (float*)d_out;
    cudaFuncSetAttribute(vq_fused, cudaFuncAttributeMaxDynamicSharedMemorySize, SMEMF);
    prep_absmax<<<256, 256>>>(cb);
    prep_quant<<<KCB / 8, 256>>>(cb);
    vq_fused<<<512, 256, SMEMF>>>(z, cb, out);
}